// round 14
// baseline (speedup 1.0000x reference)
#include <cuda_runtime.h>
#include <cuda_fp16.h>
#include <cstdint>
#include <math.h>

#define B_    2
#define N_    2048
#define E_    1024
#define H_    16
#define HD_   64
#define MTOT  (B_*N_)          // 4096

typedef __half fp16;

// ---- scratch (device globals; no allocation allowed) ----
__device__ fp16  g_xh[MTOT*E_], g_xl[MTOT*E_];       // split x
__device__ fp16  g_w[5*E_*E_];                        // fp16 Wq,Wk,Wv,Wu,Wo
__device__ fp16  g_qh[B_*H_*N_*HD_], g_ql[B_*H_*N_*HD_]; // q split [bh][n][d]
__device__ fp16  g_k[B_*H_*N_*HD_];                   // k single fp16
__device__ fp16  g_v[B_*H_*N_*HD_];                   // v single fp16 (silu)
__device__ float g_u[MTOT*E_];                        // silu(u), fp32
__device__ float g_attn[MTOT*E_];                     // attention out, fp32
__device__ fp16  g_gh[MTOT*E_], g_gl[MTOT*E_];       // split ln-gated

__device__ __forceinline__ float silu_f(float x) {
    return x / (1.0f + expf(-x));
}

// ============================================================
// helpers
// ============================================================
__device__ __forceinline__ uint32_t smem_u32(const void* p) {
    uint32_t a;
    asm("{ .reg .u64 t; cvta.to.shared.u64 t, %1; cvt.u32.u64 %0, t; }"
        : "=r"(a) : "l"(p));
    return a;
}

__device__ __forceinline__ void cp16(uint32_t smem_dst, const void* gptr) {
    asm volatile("cp.async.cg.shared.global [%0], [%1], 16;"
        :: "r"(smem_dst), "l"(gptr) : "memory");
}
#define CP_COMMIT()  asm volatile("cp.async.commit_group;" ::: "memory")
#define CP_WAIT(n)   asm volatile("cp.async.wait_group %0;" :: "n"(n) : "memory")

__device__ __forceinline__ void ldsm_x4(uint32_t& r0, uint32_t& r1,
                                        uint32_t& r2, uint32_t& r3, uint32_t a) {
    asm volatile("ldmatrix.sync.aligned.m8n8.x4.shared.b16 {%0,%1,%2,%3}, [%4];"
        : "=r"(r0), "=r"(r1), "=r"(r2), "=r"(r3) : "r"(a));
}
__device__ __forceinline__ void ldsm_x4t(uint32_t& r0, uint32_t& r1,
                                         uint32_t& r2, uint32_t& r3, uint32_t a) {
    asm volatile("ldmatrix.sync.aligned.m8n8.x4.trans.shared.b16 {%0,%1,%2,%3}, [%4];"
        : "=r"(r0), "=r"(r1), "=r"(r2), "=r"(r3) : "r"(a));
}

__device__ __forceinline__ void mma_f16(float* c, const uint32_t* a,
                                        uint32_t b0, uint32_t b1) {
    asm volatile(
        "mma.sync.aligned.m16n8k16.row.col.f32.f16.f16.f32 "
        "{%0,%1,%2,%3}, {%4,%5,%6,%7}, {%8,%9}, {%0,%1,%2,%3};"
        : "+f"(c[0]), "+f"(c[1]), "+f"(c[2]), "+f"(c[3])
        : "r"(a[0]), "r"(a[1]), "r"(a[2]), "r"(a[3]), "r"(b0), "r"(b1));
}

// split a pair of floats into hi/lo fp16x2 (packed, elem0 in low half)
__device__ __forceinline__ void split_pair(float v0, float v1,
                                           uint32_t& hi, uint32_t& lo) {
    __half h0 = __float2half_rn(v0);
    __half h1 = __float2half_rn(v1);
    __half l0 = __float2half_rn(v0 - __half2float(h0));
    __half l1 = __float2half_rn(v1 - __half2float(h1));
    __half2 hp = __halves2half2(h0, h1);
    __half2 lp = __halves2half2(l0, l1);
    hi = *reinterpret_cast<uint32_t*>(&hp);
    lo = *reinterpret_cast<uint32_t*>(&lp);
}
__device__ __forceinline__ uint32_t pack_h2(float v0, float v1) {
    __half2 p = __floats2half2_rn(v0, v1);
    return *reinterpret_cast<uint32_t*>(&p);
}

// ============================================================
// fp32 -> split fp16 conversion (x)
// ============================================================
__global__ __launch_bounds__(256) void cvt_split(
    const float4* __restrict__ src, uint32_t* __restrict__ hi,
    uint32_t* __restrict__ lo, int n4)
{
    int i = blockIdx.x * 256 + threadIdx.x;
    if (i >= n4) return;
    float4 v = src[i];
    uint32_t h0, l0, h1, l1;
    split_pair(v.x, v.y, h0, l0);
    split_pair(v.z, v.w, h1, l1);
    hi[2*i]   = h0;  hi[2*i+1] = h1;
    lo[2*i]   = l0;  lo[2*i+1] = l1;
}

// fp32 -> fp16 for all 5 weights, one launch
#define W4C (E_*E_/4)
__global__ __launch_bounds__(256) void cvt_w(
    const float4* __restrict__ w0, const float4* __restrict__ w1,
    const float4* __restrict__ w2, const float4* __restrict__ w3,
    const float4* __restrict__ w4p, uint32_t* __restrict__ dst)
{
    int i = blockIdx.x * 256 + threadIdx.x;
    if (i >= 5 * W4C) return;
    int w = i / W4C, j = i - w * W4C;
    const float4* src = (w == 0) ? w0 : (w == 1) ? w1 : (w == 2) ? w2
                       : (w == 3) ? w3 : w4p;
    float4 v = src[j];
    dst[2*i]   = pack_h2(v.x, v.y);
    dst[2*i+1] = pack_h2(v.z, v.w);
}

// ============================================================
// 2-term split-fp16 MMA GEMM: C[m,n] = sum_k A[m,k]*W[n,k] + bias[n]
// A split (Ah+Al), W single fp16. 128x128 tile, k-tile 32,
// 8 warps (2m x 4n), warp tile 64x32. Compute-then-prefetch
// 2-stage pipeline. __launch_bounds__(256,2) pins 2 CTAs/SM.
// ============================================================
#define GSTG 24576

__global__ __launch_bounds__(256, 2) void mma_gemm(
    const fp16* __restrict__ Ah, const fp16* __restrict__ Al,
    const float* __restrict__ bb0, const float* __restrict__ bb1,
    const float* __restrict__ bb2, const float* __restrict__ bb3,
    float* __restrict__ Cout, int mode)
{
    extern __shared__ char smem[];
    const int tid  = threadIdx.x;
    const int lane = tid & 31;
    const int wid  = tid >> 5;
    const int wm   = wid & 1;      // 0..1 -> m offset *64
    const int wn   = wid >> 1;     // 0..3 -> n offset *32

    const int m0 = blockIdx.y * 128;
    const int sector = (mode == 0) ? (int)(blockIdx.x >> 3) : 4;
    const int n0 = (int)(blockIdx.x & 7) * 128;
    const fp16* Wp = g_w + (size_t)sector * (E_ * E_);
    const float* bias = (mode == 1) ? bb0
        : (sector == 0 ? bb0 : sector == 1 ? bb1 : sector == 2 ? bb2 : bb3);

    uint32_t sbase = smem_u32(smem);

    float acc[4][4][4];
#pragma unroll
    for (int a = 0; a < 4; a++)
#pragma unroll
        for (int b = 0; b < 4; b++)
#pragma unroll
            for (int c = 0; c < 4; c++) acc[a][b][c] = 0.0f;

    // tile loader: 512 16B-chunks per matrix (Ah, Al, B), 2/thread each
#define LOAD_TILE(kt, stage) do {                                              \
    uint32_t sb_ = sbase + (uint32_t)(stage) * GSTG;                           \
    int kofs_ = (kt) * 32;                                                     \
    _Pragma("unroll")                                                          \
    for (int j_ = 0; j_ < 2; j_++) {                                           \
        int idx_ = tid + j_ * 256;                                             \
        int r_ = idx_ >> 2, kc_ = idx_ & 3;                                    \
        uint32_t so_ = (uint32_t)(r_ * 64 + ((kc_ ^ (r_ & 3)) << 4));          \
        size_t ga_ = (size_t)(m0 + r_) * E_ + kofs_ + kc_ * 8;                 \
        size_t gb_ = (size_t)(n0 + r_) * E_ + kofs_ + kc_ * 8;                 \
        cp16(sb_ +     0 + so_, Ah + ga_);                                     \
        cp16(sb_ +  8192 + so_, Al + ga_);                                     \
        cp16(sb_ + 16384 + so_, Wp + gb_);                                     \
    }                                                                          \
} while (0)

    // prologue: two tiles in flight
    LOAD_TILE(0, 0);  CP_COMMIT();
    LOAD_TILE(1, 1);  CP_COMMIT();

    const int mtxA = lane >> 3, lrA = lane & 7;

    for (int kt = 0; kt < 32; kt++) {
        if (kt < 31) { CP_WAIT(1); } else { CP_WAIT(0); }
        __syncthreads();

        uint32_t sA_h = sbase + (uint32_t)(kt & 1) * GSTG;
        uint32_t sA_l = sA_h + 8192;
        uint32_t sB   = sA_h + 16384;

#pragma unroll
        for (int ks = 0; ks < 2; ks++) {
            uint32_t ahf[4][4], alf[4][4], bf[4][2];
#pragma unroll
            for (int mt = 0; mt < 4; mt++) {
                int row = wm * 64 + mt * 16 + (mtxA & 1) * 8 + lrA;
                int kch = ks * 2 + (mtxA >> 1);
                uint32_t ao = (uint32_t)(row * 64 + ((kch ^ (row & 3)) << 4));
                ldsm_x4(ahf[mt][0], ahf[mt][1], ahf[mt][2], ahf[mt][3], sA_h + ao);
                ldsm_x4(alf[mt][0], alf[mt][1], alf[mt][2], alf[mt][3], sA_l + ao);
            }
            // B: pair two nt tiles per x4 (lanes 0-15 -> nt, 16-31 -> nt+1)
#pragma unroll
            for (int np = 0; np < 2; np++) {
                int nt_eff = np * 2 + (lane >> 4);
                int row = wn * 32 + nt_eff * 8 + (lane & 7);
                int kch = ks * 2 + ((lane >> 3) & 1);
                uint32_t bo = (uint32_t)(row * 64 + ((kch ^ (row & 3)) << 4));
                ldsm_x4(bf[np*2][0], bf[np*2][1], bf[np*2+1][0], bf[np*2+1][1],
                        sB + bo);
            }
#pragma unroll
            for (int mt = 0; mt < 4; mt++)
#pragma unroll
                for (int nt = 0; nt < 4; nt++) {
                    mma_f16(acc[mt][nt], ahf[mt], bf[nt][0], bf[nt][1]);
                    mma_f16(acc[mt][nt], alf[mt], bf[nt][0], bf[nt][1]);
                }
        }
        __syncthreads();
        if (kt + 2 < 32) { LOAD_TILE(kt + 2, kt & 1); CP_COMMIT(); }
    }

    // ---- epilogue ----
#pragma unroll
    for (int mt = 0; mt < 4; mt++) {
#pragma unroll
        for (int half = 0; half < 2; half++) {
            int m = m0 + wm * 64 + mt * 16 + (lane >> 2) + half * 8;
#pragma unroll
            for (int nt = 0; nt < 4; nt++) {
                int e = n0 + wn * 32 + nt * 8 + (lane & 3) * 2;
                float v0 = acc[mt][nt][half * 2 + 0] + bias[e];
                float v1 = acc[mt][nt][half * 2 + 1] + bias[e + 1];
                if (mode == 1) {
                    float2 o = make_float2(v0, v1);
                    *(float2*)(Cout + (size_t)m * E_ + e) = o;
                } else if (sector == 3) {
                    float2 o = make_float2(silu_f(v0), silu_f(v1));
                    *(float2*)(g_u + (size_t)m * E_ + e) = o;
                } else {
                    int b  = m >> 11;
                    int nn = m & 2047;
                    int h  = e >> 6, d = e & 63;
                    size_t ofs = (((size_t)(b * H_ + h)) * N_ + nn) * HD_ + d;
                    if (sector == 0) {            // q: split
                        uint32_t hi, lo;
                        split_pair(v0, v1, hi, lo);
                        *(uint32_t*)(g_qh + ofs) = hi;
                        *(uint32_t*)(g_ql + ofs) = lo;
                    } else if (sector == 1) {     // k: single
                        *(uint32_t*)(g_k + ofs) = pack_h2(v0, v1);
                    } else {                      // v: silu, single
                        *(uint32_t*)(g_v + ofs) = pack_h2(silu_f(v0), silu_f(v1));
                    }
                }
            }
        }
    }
#undef LOAD_TILE
}

// ============================================================
// 2-term split-fp16 MMA attention: O = relu(Q K^T / 8) V
// Q split (regs), K single, S split (regs), V single.
// CTA: 128 q-rows (8 warps x 16), kv in 128-chunks,
// double-buffered K/V, S in 64-kv halves.
// __launch_bounds__(256,2) pins 2 CTAs/SM (the R13 regression fix).
// smem: Qh,Ql 16KB each + K[2],V[2] 16KB each = 96KB.
// ============================================================
#define AT_Q_H  0
#define AT_Q_L  16384
#define AT_K(s) (32768 + (s) * 16384)
#define AT_V(s) (65536 + (s) * 16384)
#define AT_SMEM 98304

__global__ __launch_bounds__(256, 2) void mma_attn()
{
    extern __shared__ char smem[];
    const int tid  = threadIdx.x;
    const int lane = tid & 31;
    const int wid  = tid >> 5;

    const int qt = blockIdx.x;       // 0..15
    const int bh = blockIdx.y;       // 0..31
    const int q0 = qt * 128;
    const size_t bhofs = (size_t)bh * N_ * HD_;

    uint32_t sbase = smem_u32(smem);

    // kv chunk loader into stage s
#define LOAD_KV(ch, s) do {                                                    \
    _Pragma("unroll")                                                          \
    for (int j_ = 0; j_ < 4; j_++) {                                           \
        int idx_ = tid + j_ * 256;                                             \
        int r_ = idx_ >> 3, kc_ = idx_ & 7;                                    \
        uint32_t so_ = (uint32_t)(r_ * 128 + ((kc_ ^ (r_ & 7)) << 4));         \
        size_t g_ = bhofs + (size_t)((ch) * 128 + r_) * HD_ + kc_ * 8;         \
        cp16(sbase + AT_K(s) + so_, g_k + g_);                                 \
        cp16(sbase + AT_V(s) + so_, g_v + g_);                                 \
    }                                                                          \
} while (0)

    // ---- load Q tile (hi+lo) ----
#pragma unroll
    for (int j = 0; j < 4; j++) {
        int idx = tid + j * 256;           // 0..1023
        int r = idx >> 3, kc = idx & 7;
        uint32_t so = (uint32_t)(r * 128 + ((kc ^ (r & 7)) << 4));
        size_t g = bhofs + (size_t)(q0 + r) * HD_ + kc * 8;
        cp16(sbase + AT_Q_H + so, g_qh + g);
        cp16(sbase + AT_Q_L + so, g_ql + g);
    }
    CP_COMMIT();
    LOAD_KV(0, 0); CP_COMMIT();
    LOAD_KV(1, 1); CP_COMMIT();

    CP_WAIT(2);        // Q done
    __syncthreads();

    // ---- Q fragments (persist in regs): 4 ksteps x x4, hi+lo ----
    uint32_t qfh[4][4], qfl[4][4];
    {
        const int mtx = lane >> 3, lr = lane & 7;
#pragma unroll
        for (int ks = 0; ks < 4; ks++) {
            int row = wid * 16 + (mtx & 1) * 8 + lr;
            int kch = ks * 2 + (mtx >> 1);
            uint32_t ao = (uint32_t)(row * 128 + ((kch ^ (row & 7)) << 4));
            ldsm_x4(qfh[ks][0], qfh[ks][1], qfh[ks][2], qfh[ks][3], sbase + AT_Q_H + ao);
            ldsm_x4(qfl[ks][0], qfl[ks][1], qfl[ks][2], qfl[ks][3], sbase + AT_Q_L + ao);
        }
    }

    float accO[8][4];
#pragma unroll
    for (int i = 0; i < 8; i++)
#pragma unroll
        for (int j = 0; j < 4; j++) accO[i][j] = 0.0f;

    for (int ch = 0; ch < 16; ch++) {
        if (ch < 14) { CP_WAIT(1); } else { CP_WAIT(0); }
        __syncthreads();

        uint32_t sK = sbase + AT_K(ch & 1);
        uint32_t sV = sbase + AT_V(ch & 1);

        // two 64-kv halves; S lives only within a half (32 regs)
#pragma unroll
        for (int half = 0; half < 2; half++) {
            float sacc[8][4];
            // ---- S = Q K^T : nt pairs via ldsm x4 ----
#pragma unroll
            for (int np = 0; np < 4; np++) {
#pragma unroll
                for (int i = 0; i < 4; i++) {
                    sacc[np*2][i]   = 0.0f;
                    sacc[np*2+1][i] = 0.0f;
                }
                uint32_t kf[4][4];
#pragma unroll
                for (int ks = 0; ks < 4; ks++) {
                    int nt_eff = half * 8 + np * 2 + (lane >> 4);
                    int row = nt_eff * 8 + (lane & 7);
                    int kch = ks * 2 + ((lane >> 3) & 1);
                    uint32_t bo = (uint32_t)(row * 128 + ((kch ^ (row & 7)) << 4));
                    ldsm_x4(kf[ks][0], kf[ks][1], kf[ks][2], kf[ks][3], sK + bo);
                }
#pragma unroll
                for (int ks = 0; ks < 4; ks++) {
                    mma_f16(sacc[np*2],   qfh[ks], kf[ks][0], kf[ks][1]);
                    mma_f16(sacc[np*2],   qfl[ks], kf[ks][0], kf[ks][1]);
                    mma_f16(sacc[np*2+1], qfh[ks], kf[ks][2], kf[ks][3]);
                    mma_f16(sacc[np*2+1], qfl[ks], kf[ks][2], kf[ks][3]);
                }
            }
            // scale + relu
#pragma unroll
            for (int nt = 0; nt < 8; nt++)
#pragma unroll
                for (int i = 0; i < 4; i++) {
                    float s = sacc[nt][i] * 0.125f;
                    sacc[nt][i] = s > 0.0f ? s : 0.0f;
                }

            // ---- O += S V over this half's 64 kv rows ----
#pragma unroll
            for (int kbl = 0; kbl < 4; kbl++) {
                int kb = half * 4 + kbl;
                uint32_t ah[4], al[4];
                split_pair(sacc[2*kbl][0],   sacc[2*kbl][1],   ah[0], al[0]);
                split_pair(sacc[2*kbl][2],   sacc[2*kbl][3],   ah[1], al[1]);
                split_pair(sacc[2*kbl+1][0], sacc[2*kbl+1][1], ah[2], al[2]);
                split_pair(sacc[2*kbl+1][2], sacc[2*kbl+1][3], ah[3], al[3]);
#pragma unroll
                for (int dp = 0; dp < 4; dp++) {
                    int kvrow = kb * 16 + (lane & 15);
                    int dte = dp * 2 + (lane >> 4);
                    uint32_t vo = (uint32_t)(kvrow * 128 + ((dte ^ (kvrow & 7)) << 4));
                    uint32_t v0, v1, v2, v3;
                    ldsm_x4t(v0, v1, v2, v3, sV + vo);
                    mma_f16(accO[dp*2],   ah, v0, v1);
                    mma_f16(accO[dp*2],   al, v0, v1);
                    mma_f16(accO[dp*2+1], ah, v2, v3);
                    mma_f16(accO[dp*2+1], al, v2, v3);
                }
            }
        }

        __syncthreads();
        if (ch + 2 < 16) { LOAD_KV(ch + 2, ch & 1); CP_COMMIT(); }
    }

    // ---- write O -> g_attn [b][n][h*64+d] ----
    const int b = bh >> 4;
    const int h = bh & 15;
#pragma unroll
    for (int dt = 0; dt < 8; dt++) {
        int d = dt * 8 + (lane & 3) * 2;
#pragma unroll
        for (int half = 0; half < 2; half++) {
            int q = q0 + wid * 16 + (lane >> 2) + half * 8;
            float2 o = make_float2(accO[dt][half * 2], accO[dt][half * 2 + 1]);
            *(float2*)(g_attn + ((size_t)(b * N_ + q)) * E_ + h * HD_ + d) = o;
        }
    }
#undef LOAD_KV
}

// ============================================================
// LayerNorm + gate -> split fp16 (g_gh/g_gl)
// ============================================================
__global__ __launch_bounds__(256) void ln_gate(
    const float* __restrict__ ln_g, const float* __restrict__ ln_b)
{
    const int row = blockIdx.x;
    const int c   = threadIdx.x * 4;
    const float* xr = g_attn + (size_t)row * E_;

    float4 a = *(const float4*)(xr + c);
    float sum = a.x + a.y + a.z + a.w;
    float sq  = a.x * a.x + a.y * a.y + a.z * a.z + a.w * a.w;

#pragma unroll
    for (int off = 16; off > 0; off >>= 1) {
        sum += __shfl_xor_sync(0xffffffff, sum, off);
        sq  += __shfl_xor_sync(0xffffffff, sq,  off);
    }
    __shared__ float s1[8], s2[8];
    int wid = threadIdx.x >> 5, lid = threadIdx.x & 31;
    if (lid == 0) { s1[wid] = sum; s2[wid] = sq; }
    __syncthreads();
    if (threadIdx.x < 8) {
        sum = s1[threadIdx.x]; sq = s2[threadIdx.x];
#pragma unroll
        for (int off = 4; off > 0; off >>= 1) {
            sum += __shfl_xor_sync(0xff, sum, off);
            sq  += __shfl_xor_sync(0xff, sq,  off);
        }
        if (threadIdx.x == 0) { s1[0] = sum; s2[0] = sq; }
    }
    __syncthreads();
    sum = s1[0]; sq = s2[0];

    float mean = sum * (1.0f / E_);
    float var  = sq * (1.0f / E_) - mean * mean;
    float inv  = rsqrtf(var + 1e-5f);

    float4 g4 = *(const float4*)(ln_g + c);
    float4 b4 = *(const float4*)(ln_b + c);
    float4 u4 = *(const float4*)(g_u + (size_t)row * E_ + c);
    float v0 = ((a.x - mean) * inv * g4.x + b4.x) * u4.x;
    float v1 = ((a.y - mean) * inv * g4.y + b4.y) * u4.y;
    float v2 = ((a.z - mean) * inv * g4.z + b4.z) * u4.z;
    float v3 = ((a.w - mean) * inv * g4.w + b4.w) * u4.w;

    uint32_t h0, l0, h1, l1;
    split_pair(v0, v1, h0, l0);
    split_pair(v2, v3, h1, l1);
    size_t ofs = (size_t)row * E_ + c;
    *(uint32_t*)(g_gh + ofs)     = h0;
    *(uint32_t*)(g_gh + ofs + 2) = h1;
    *(uint32_t*)(g_gl + ofs)     = l0;
    *(uint32_t*)(g_gl + ofs + 2) = l1;
}

// ============================================================
extern "C" void kernel_launch(void* const* d_in, const int* in_sizes, int n_in,
                              void* d_out, int out_size)
{
    const float* x    = (const float*)d_in[0];
    const float* Wq   = (const float*)d_in[1];
    const float* bq   = (const float*)d_in[2];
    const float* Wk   = (const float*)d_in[3];
    const float* bk   = (const float*)d_in[4];
    const float* Wv   = (const float*)d_in[5];
    const float* bv   = (const float*)d_in[6];
    const float* Wu   = (const float*)d_in[7];
    const float* bu   = (const float*)d_in[8];
    const float* Wo   = (const float*)d_in[9];
    const float* bo   = (const float*)d_in[10];
    const float* lng  = (const float*)d_in[11];
    const float* lnb  = (const float*)d_in[12];
    float* out = (float*)d_out;

    cudaFuncSetAttribute(mma_gemm, cudaFuncAttributeMaxDynamicSharedMemorySize, 2 * GSTG);
    cudaFuncSetAttribute(mma_attn, cudaFuncAttributeMaxDynamicSharedMemorySize, AT_SMEM);

    fp16 *xh_p, *xl_p, *w_p, *gh_p, *gl_p;
    cudaGetSymbolAddress((void**)&xh_p, g_xh);
    cudaGetSymbolAddress((void**)&xl_p, g_xl);
    cudaGetSymbolAddress((void**)&w_p,  g_w);
    cudaGetSymbolAddress((void**)&gh_p, g_gh);
    cudaGetSymbolAddress((void**)&gl_p, g_gl);

    // 0) convert: x -> split fp16; 5 weights -> fp16 (single launch)
    {
        int n4 = (MTOT * E_) / 4;
        cvt_split<<<n4 / 256, 256>>>((const float4*)x,
            (uint32_t*)xh_p, (uint32_t*)xl_p, n4);
        cvt_w<<<(5 * W4C + 255) / 256, 256>>>(
            (const float4*)Wq, (const float4*)Wk, (const float4*)Wv,
            (const float4*)Wu, (const float4*)Wo, (uint32_t*)w_p);
    }

    // 1) fused QKVU projections: grid x = 4 sectors x 8 n-tiles, y = 32 m-tiles
    mma_gemm<<<dim3(32, 32), 256, 2 * GSTG>>>(
        xh_p, xl_p, bq, bk, bv, bu, nullptr, 0);

    // 2) relu-attention on tensor cores
    mma_attn<<<dim3(16, 32), 256, AT_SMEM>>>();

    // 3) layernorm + gate (writes split fp16)
    ln_gate<<<MTOT, 256>>>(lng, lnb);

    // 4) output projection
    mma_gemm<<<dim3(8, 32), 256, 2 * GSTG>>>(
        gh_p, gl_p, bo, nullptr, nullptr, nullptr, out, 1);
}

// round 15
// speedup vs baseline: 1.5695x; 1.5695x over previous
#include <cuda_runtime.h>
#include <cuda_fp16.h>
#include <cstdint>
#include <math.h>

#define B_    2
#define N_    2048
#define E_    1024
#define H_    16
#define HD_   64
#define MTOT  (B_*N_)          // 4096

typedef __half fp16;

// ---- scratch (device globals; no allocation allowed) ----
__device__ fp16  g_xh[MTOT*E_], g_xl[MTOT*E_];       // split x
__device__ fp16  g_w[5*E_*E_];                        // fp16 Wq,Wk,Wv,Wu,Wo
__device__ fp16  g_qh[B_*H_*N_*HD_], g_ql[B_*H_*N_*HD_]; // q split [bh][n][d]
__device__ fp16  g_k[B_*H_*N_*HD_];                   // k single fp16
__device__ fp16  g_v[B_*H_*N_*HD_];                   // v single fp16 (silu)
__device__ float g_u[MTOT*E_];                        // silu(u), fp32
__device__ float g_attn[MTOT*E_];                     // attention out, fp32
__device__ fp16  g_gh[MTOT*E_], g_gl[MTOT*E_];       // split ln-gated

__device__ __forceinline__ float silu_f(float x) {
    return x / (1.0f + expf(-x));
}

// ============================================================
// helpers
// ============================================================
__device__ __forceinline__ uint32_t smem_u32(const void* p) {
    uint32_t a;
    asm("{ .reg .u64 t; cvta.to.shared.u64 t, %1; cvt.u32.u64 %0, t; }"
        : "=r"(a) : "l"(p));
    return a;
}

__device__ __forceinline__ void cp16(uint32_t smem_dst, const void* gptr) {
    asm volatile("cp.async.cg.shared.global [%0], [%1], 16;"
        :: "r"(smem_dst), "l"(gptr) : "memory");
}
#define CP_COMMIT()  asm volatile("cp.async.commit_group;" ::: "memory")
#define CP_WAIT(n)   asm volatile("cp.async.wait_group %0;" :: "n"(n) : "memory")

__device__ __forceinline__ void ldsm_x4(uint32_t& r0, uint32_t& r1,
                                        uint32_t& r2, uint32_t& r3, uint32_t a) {
    asm volatile("ldmatrix.sync.aligned.m8n8.x4.shared.b16 {%0,%1,%2,%3}, [%4];"
        : "=r"(r0), "=r"(r1), "=r"(r2), "=r"(r3) : "r"(a));
}
__device__ __forceinline__ void ldsm_x4t(uint32_t& r0, uint32_t& r1,
                                         uint32_t& r2, uint32_t& r3, uint32_t a) {
    asm volatile("ldmatrix.sync.aligned.m8n8.x4.trans.shared.b16 {%0,%1,%2,%3}, [%4];"
        : "=r"(r0), "=r"(r1), "=r"(r2), "=r"(r3) : "r"(a));
}

__device__ __forceinline__ void mma_f16(float* c, const uint32_t* a,
                                        uint32_t b0, uint32_t b1) {
    asm volatile(
        "mma.sync.aligned.m16n8k16.row.col.f32.f16.f16.f32 "
        "{%0,%1,%2,%3}, {%4,%5,%6,%7}, {%8,%9}, {%0,%1,%2,%3};"
        : "+f"(c[0]), "+f"(c[1]), "+f"(c[2]), "+f"(c[3])
        : "r"(a[0]), "r"(a[1]), "r"(a[2]), "r"(a[3]), "r"(b0), "r"(b1));
}

// split a pair of floats into hi/lo fp16x2 (packed, elem0 in low half)
__device__ __forceinline__ void split_pair(float v0, float v1,
                                           uint32_t& hi, uint32_t& lo) {
    __half h0 = __float2half_rn(v0);
    __half h1 = __float2half_rn(v1);
    __half l0 = __float2half_rn(v0 - __half2float(h0));
    __half l1 = __float2half_rn(v1 - __half2float(h1));
    __half2 hp = __halves2half2(h0, h1);
    __half2 lp = __halves2half2(l0, l1);
    hi = *reinterpret_cast<uint32_t*>(&hp);
    lo = *reinterpret_cast<uint32_t*>(&lp);
}
__device__ __forceinline__ uint32_t pack_h2(float v0, float v1) {
    __half2 p = __floats2half2_rn(v0, v1);
    return *reinterpret_cast<uint32_t*>(&p);
}

// ============================================================
// fp32 -> split fp16 conversion (x)
// ============================================================
__global__ __launch_bounds__(256) void cvt_split(
    const float4* __restrict__ src, uint32_t* __restrict__ hi,
    uint32_t* __restrict__ lo, int n4)
{
    int i = blockIdx.x * 256 + threadIdx.x;
    if (i >= n4) return;
    float4 v = src[i];
    uint32_t h0, l0, h1, l1;
    split_pair(v.x, v.y, h0, l0);
    split_pair(v.z, v.w, h1, l1);
    hi[2*i]   = h0;  hi[2*i+1] = h1;
    lo[2*i]   = l0;  lo[2*i+1] = l1;
}

// fp32 -> fp16 for all 5 weights, one launch
#define W4C (E_*E_/4)
__global__ __launch_bounds__(256) void cvt_w(
    const float4* __restrict__ w0, const float4* __restrict__ w1,
    const float4* __restrict__ w2, const float4* __restrict__ w3,
    const float4* __restrict__ w4p, uint32_t* __restrict__ dst)
{
    int i = blockIdx.x * 256 + threadIdx.x;
    if (i >= 5 * W4C) return;
    int w = i / W4C, j = i - w * W4C;
    const float4* src = (w == 0) ? w0 : (w == 1) ? w1 : (w == 2) ? w2
                       : (w == 3) ? w3 : w4p;
    float4 v = src[j];
    dst[2*i]   = pack_h2(v.x, v.y);
    dst[2*i+1] = pack_h2(v.z, v.w);
}

// ============================================================
// 2-term split-fp16 MMA GEMM: C[m,n] = sum_k A[m,k]*W[n,k] + bias[n]
// A split (Ah+Al), W single fp16. 128x128 tile, k-tile 32,
// 8 warps (2m x 4n), warp tile 64x32. R12 schedule (prefetch kt+1
// at loop top), x4-paired B ldmatrix. No occupancy forcing.
// ============================================================
#define GSTG 24576

__global__ __launch_bounds__(256) void mma_gemm(
    const fp16* __restrict__ Ah, const fp16* __restrict__ Al,
    const float* __restrict__ bb0, const float* __restrict__ bb1,
    const float* __restrict__ bb2, const float* __restrict__ bb3,
    float* __restrict__ Cout, int mode)
{
    extern __shared__ char smem[];
    const int tid  = threadIdx.x;
    const int lane = tid & 31;
    const int wid  = tid >> 5;
    const int wm   = wid & 1;      // 0..1 -> m offset *64
    const int wn   = wid >> 1;     // 0..3 -> n offset *32

    const int m0 = blockIdx.y * 128;
    const int sector = (mode == 0) ? (int)(blockIdx.x >> 3) : 4;
    const int n0 = (int)(blockIdx.x & 7) * 128;
    const fp16* Wp = g_w + (size_t)sector * (E_ * E_);
    const float* bias = (mode == 1) ? bb0
        : (sector == 0 ? bb0 : sector == 1 ? bb1 : sector == 2 ? bb2 : bb3);

    uint32_t sbase = smem_u32(smem);

    float acc[4][4][4];
#pragma unroll
    for (int a = 0; a < 4; a++)
#pragma unroll
        for (int b = 0; b < 4; b++)
#pragma unroll
            for (int c = 0; c < 4; c++) acc[a][b][c] = 0.0f;

    // tile loader: 512 16B-chunks per matrix (Ah, Al, B), 2/thread each
#define LOAD_TILE(kt, stage) do {                                              \
    uint32_t sb_ = sbase + (uint32_t)(stage) * GSTG;                           \
    int kofs_ = (kt) * 32;                                                     \
    _Pragma("unroll")                                                          \
    for (int j_ = 0; j_ < 2; j_++) {                                           \
        int idx_ = tid + j_ * 256;                                             \
        int r_ = idx_ >> 2, kc_ = idx_ & 3;                                    \
        uint32_t so_ = (uint32_t)(r_ * 64 + ((kc_ ^ (r_ & 3)) << 4));          \
        size_t ga_ = (size_t)(m0 + r_) * E_ + kofs_ + kc_ * 8;                 \
        size_t gb_ = (size_t)(n0 + r_) * E_ + kofs_ + kc_ * 8;                 \
        cp16(sb_ +     0 + so_, Ah + ga_);                                     \
        cp16(sb_ +  8192 + so_, Al + ga_);                                     \
        cp16(sb_ + 16384 + so_, Wp + gb_);                                     \
    }                                                                          \
} while (0)

    LOAD_TILE(0, 0);
    CP_COMMIT();

    const int mtxA = lane >> 3, lrA = lane & 7;

    for (int kt = 0; kt < 32; kt++) {
        if (kt + 1 < 32) { LOAD_TILE(kt + 1, (kt + 1) & 1); CP_COMMIT(); }
        if (kt + 1 < 32) { CP_WAIT(1); } else { CP_WAIT(0); }
        __syncthreads();

        uint32_t sA_h = sbase + (uint32_t)(kt & 1) * GSTG;
        uint32_t sA_l = sA_h + 8192;
        uint32_t sB   = sA_h + 16384;

#pragma unroll
        for (int ks = 0; ks < 2; ks++) {
            uint32_t ahf[4][4], alf[4][4], bf[4][2];
#pragma unroll
            for (int mt = 0; mt < 4; mt++) {
                int row = wm * 64 + mt * 16 + (mtxA & 1) * 8 + lrA;
                int kch = ks * 2 + (mtxA >> 1);
                uint32_t ao = (uint32_t)(row * 64 + ((kch ^ (row & 3)) << 4));
                ldsm_x4(ahf[mt][0], ahf[mt][1], ahf[mt][2], ahf[mt][3], sA_h + ao);
                ldsm_x4(alf[mt][0], alf[mt][1], alf[mt][2], alf[mt][3], sA_l + ao);
            }
            // B: pair two nt tiles per x4 (lanes 0-15 -> nt, 16-31 -> nt+1)
#pragma unroll
            for (int np = 0; np < 2; np++) {
                int nt_eff = np * 2 + (lane >> 4);
                int row = wn * 32 + nt_eff * 8 + (lane & 7);
                int kch = ks * 2 + ((lane >> 3) & 1);
                uint32_t bo = (uint32_t)(row * 64 + ((kch ^ (row & 3)) << 4));
                ldsm_x4(bf[np*2][0], bf[np*2][1], bf[np*2+1][0], bf[np*2+1][1],
                        sB + bo);
            }
#pragma unroll
            for (int mt = 0; mt < 4; mt++)
#pragma unroll
                for (int nt = 0; nt < 4; nt++) {
                    mma_f16(acc[mt][nt], ahf[mt], bf[nt][0], bf[nt][1]);
                    mma_f16(acc[mt][nt], alf[mt], bf[nt][0], bf[nt][1]);
                }
        }
        __syncthreads();
    }

    // ---- epilogue ----
#pragma unroll
    for (int mt = 0; mt < 4; mt++) {
#pragma unroll
        for (int half = 0; half < 2; half++) {
            int m = m0 + wm * 64 + mt * 16 + (lane >> 2) + half * 8;
#pragma unroll
            for (int nt = 0; nt < 4; nt++) {
                int e = n0 + wn * 32 + nt * 8 + (lane & 3) * 2;
                float v0 = acc[mt][nt][half * 2 + 0] + bias[e];
                float v1 = acc[mt][nt][half * 2 + 1] + bias[e + 1];
                if (mode == 1) {
                    float2 o = make_float2(v0, v1);
                    *(float2*)(Cout + (size_t)m * E_ + e) = o;
                } else if (sector == 3) {
                    float2 o = make_float2(silu_f(v0), silu_f(v1));
                    *(float2*)(g_u + (size_t)m * E_ + e) = o;
                } else {
                    int b  = m >> 11;
                    int nn = m & 2047;
                    int h  = e >> 6, d = e & 63;
                    size_t ofs = (((size_t)(b * H_ + h)) * N_ + nn) * HD_ + d;
                    if (sector == 0) {            // q: split
                        uint32_t hi, lo;
                        split_pair(v0, v1, hi, lo);
                        *(uint32_t*)(g_qh + ofs) = hi;
                        *(uint32_t*)(g_ql + ofs) = lo;
                    } else if (sector == 1) {     // k: single
                        *(uint32_t*)(g_k + ofs) = pack_h2(v0, v1);
                    } else {                      // v: silu, single
                        *(uint32_t*)(g_v + ofs) = pack_h2(silu_f(v0), silu_f(v1));
                    }
                }
            }
        }
    }
#undef LOAD_TILE
}

// ============================================================
// 2-term split-fp16 MMA attention: O = relu(Q K^T / 8) V
// Q split (regs), K single, S split (regs), V single.
// CTA: 128 q-rows (8 warps x 16), kv in 128-chunks.
// SINGLE-buffered K/V (R12 flow, keeps 2 CTAs/SM) with the
// halved-S + x4-paired ldmatrix inner loop (R13's, fewer regs/issues).
// smem: Qh,Ql,K,V each 16KB -> 64KB.
// ============================================================
#define AT_Q_H  0
#define AT_Q_L  16384
#define AT_K    32768
#define AT_V    49152
#define AT_SMEM 65536

__global__ __launch_bounds__(256) void mma_attn()
{
    extern __shared__ char smem[];
    const int tid  = threadIdx.x;
    const int lane = tid & 31;
    const int wid  = tid >> 5;

    const int qt = blockIdx.x;       // 0..15
    const int bh = blockIdx.y;       // 0..31
    const int q0 = qt * 128;
    const size_t bhofs = (size_t)bh * N_ * HD_;

    uint32_t sbase = smem_u32(smem);

    // ---- load Q tile (hi+lo) ----
#pragma unroll
    for (int j = 0; j < 4; j++) {
        int idx = tid + j * 256;           // 0..1023
        int r = idx >> 3, kc = idx & 7;
        uint32_t so = (uint32_t)(r * 128 + ((kc ^ (r & 7)) << 4));
        size_t g = bhofs + (size_t)(q0 + r) * HD_ + kc * 8;
        cp16(sbase + AT_Q_H + so, g_qh + g);
        cp16(sbase + AT_Q_L + so, g_ql + g);
    }
    CP_COMMIT(); CP_WAIT(0);
    __syncthreads();

    // ---- Q fragments (persist in regs): 4 ksteps x x4, hi+lo ----
    uint32_t qfh[4][4], qfl[4][4];
    {
        const int mtx = lane >> 3, lr = lane & 7;
#pragma unroll
        for (int ks = 0; ks < 4; ks++) {
            int row = wid * 16 + (mtx & 1) * 8 + lr;
            int kch = ks * 2 + (mtx >> 1);
            uint32_t ao = (uint32_t)(row * 128 + ((kch ^ (row & 7)) << 4));
            ldsm_x4(qfh[ks][0], qfh[ks][1], qfh[ks][2], qfh[ks][3], sbase + AT_Q_H + ao);
            ldsm_x4(qfl[ks][0], qfl[ks][1], qfl[ks][2], qfl[ks][3], sbase + AT_Q_L + ao);
        }
    }

    float accO[8][4];
#pragma unroll
    for (int i = 0; i < 8; i++)
#pragma unroll
        for (int j = 0; j < 4; j++) accO[i][j] = 0.0f;

    for (int ch = 0; ch < 16; ch++) {
        __syncthreads();   // prior compute done before K/V overwrite
#pragma unroll
        for (int j = 0; j < 4; j++) {
            int idx = tid + j * 256;
            int r = idx >> 3, kc = idx & 7;
            uint32_t so = (uint32_t)(r * 128 + ((kc ^ (r & 7)) << 4));
            size_t g = bhofs + (size_t)(ch * 128 + r) * HD_ + kc * 8;
            cp16(sbase + AT_K + so, g_k + g);
            cp16(sbase + AT_V + so, g_v + g);
        }
        CP_COMMIT(); CP_WAIT(0);
        __syncthreads();

        uint32_t sK = sbase + AT_K;
        uint32_t sV = sbase + AT_V;

        // two 64-kv halves; S lives only within a half (32 regs)
#pragma unroll
        for (int half = 0; half < 2; half++) {
            float sacc[8][4];
            // ---- S = Q K^T : nt pairs via ldsm x4 ----
#pragma unroll
            for (int np = 0; np < 4; np++) {
#pragma unroll
                for (int i = 0; i < 4; i++) {
                    sacc[np*2][i]   = 0.0f;
                    sacc[np*2+1][i] = 0.0f;
                }
                uint32_t kf[4][4];
#pragma unroll
                for (int ks = 0; ks < 4; ks++) {
                    int nt_eff = half * 8 + np * 2 + (lane >> 4);
                    int row = nt_eff * 8 + (lane & 7);
                    int kch = ks * 2 + ((lane >> 3) & 1);
                    uint32_t bo = (uint32_t)(row * 128 + ((kch ^ (row & 7)) << 4));
                    ldsm_x4(kf[ks][0], kf[ks][1], kf[ks][2], kf[ks][3], sK + bo);
                }
#pragma unroll
                for (int ks = 0; ks < 4; ks++) {
                    mma_f16(sacc[np*2],   qfh[ks], kf[ks][0], kf[ks][1]);
                    mma_f16(sacc[np*2],   qfl[ks], kf[ks][0], kf[ks][1]);
                    mma_f16(sacc[np*2+1], qfh[ks], kf[ks][2], kf[ks][3]);
                    mma_f16(sacc[np*2+1], qfl[ks], kf[ks][2], kf[ks][3]);
                }
            }
            // scale + relu
#pragma unroll
            for (int nt = 0; nt < 8; nt++)
#pragma unroll
                for (int i = 0; i < 4; i++) {
                    float s = sacc[nt][i] * 0.125f;
                    sacc[nt][i] = s > 0.0f ? s : 0.0f;
                }

            // ---- O += S V over this half's 64 kv rows ----
#pragma unroll
            for (int kbl = 0; kbl < 4; kbl++) {
                int kb = half * 4 + kbl;
                uint32_t ah[4], al[4];
                split_pair(sacc[2*kbl][0],   sacc[2*kbl][1],   ah[0], al[0]);
                split_pair(sacc[2*kbl][2],   sacc[2*kbl][3],   ah[1], al[1]);
                split_pair(sacc[2*kbl+1][0], sacc[2*kbl+1][1], ah[2], al[2]);
                split_pair(sacc[2*kbl+1][2], sacc[2*kbl+1][3], ah[3], al[3]);
#pragma unroll
                for (int dp = 0; dp < 4; dp++) {
                    int kvrow = kb * 16 + (lane & 15);
                    int dte = dp * 2 + (lane >> 4);
                    uint32_t vo = (uint32_t)(kvrow * 128 + ((dte ^ (kvrow & 7)) << 4));
                    uint32_t v0, v1, v2, v3;
                    ldsm_x4t(v0, v1, v2, v3, sV + vo);
                    mma_f16(accO[dp*2],   ah, v0, v1);
                    mma_f16(accO[dp*2],   al, v0, v1);
                    mma_f16(accO[dp*2+1], ah, v2, v3);
                    mma_f16(accO[dp*2+1], al, v2, v3);
                }
            }
        }
    }

    // ---- write O -> g_attn [b][n][h*64+d] ----
    const int b = bh >> 4;
    const int h = bh & 15;
#pragma unroll
    for (int dt = 0; dt < 8; dt++) {
        int d = dt * 8 + (lane & 3) * 2;
#pragma unroll
        for (int half = 0; half < 2; half++) {
            int q = q0 + wid * 16 + (lane >> 2) + half * 8;
            float2 o = make_float2(accO[dt][half * 2], accO[dt][half * 2 + 1]);
            *(float2*)(g_attn + ((size_t)(b * N_ + q)) * E_ + h * HD_ + d) = o;
        }
    }
}

// ============================================================
// LayerNorm + gate -> split fp16 (g_gh/g_gl)
// ============================================================
__global__ __launch_bounds__(256) void ln_gate(
    const float* __restrict__ ln_g, const float* __restrict__ ln_b)
{
    const int row = blockIdx.x;
    const int c   = threadIdx.x * 4;
    const float* xr = g_attn + (size_t)row * E_;

    float4 a = *(const float4*)(xr + c);
    float sum = a.x + a.y + a.z + a.w;
    float sq  = a.x * a.x + a.y * a.y + a.z * a.z + a.w * a.w;

#pragma unroll
    for (int off = 16; off > 0; off >>= 1) {
        sum += __shfl_xor_sync(0xffffffff, sum, off);
        sq  += __shfl_xor_sync(0xffffffff, sq,  off);
    }
    __shared__ float s1[8], s2[8];
    int wid = threadIdx.x >> 5, lid = threadIdx.x & 31;
    if (lid == 0) { s1[wid] = sum; s2[wid] = sq; }
    __syncthreads();
    if (threadIdx.x < 8) {
        sum = s1[threadIdx.x]; sq = s2[threadIdx.x];
#pragma unroll
        for (int off = 4; off > 0; off >>= 1) {
            sum += __shfl_xor_sync(0xff, sum, off);
            sq  += __shfl_xor_sync(0xff, sq,  off);
        }
        if (threadIdx.x == 0) { s1[0] = sum; s2[0] = sq; }
    }
    __syncthreads();
    sum = s1[0]; sq = s2[0];

    float mean = sum * (1.0f / E_);
    float var  = sq * (1.0f / E_) - mean * mean;
    float inv  = rsqrtf(var + 1e-5f);

    float4 g4 = *(const float4*)(ln_g + c);
    float4 b4 = *(const float4*)(ln_b + c);
    float4 u4 = *(const float4*)(g_u + (size_t)row * E_ + c);
    float v0 = ((a.x - mean) * inv * g4.x + b4.x) * u4.x;
    float v1 = ((a.y - mean) * inv * g4.y + b4.y) * u4.y;
    float v2 = ((a.z - mean) * inv * g4.z + b4.z) * u4.z;
    float v3 = ((a.w - mean) * inv * g4.w + b4.w) * u4.w;

    uint32_t h0, l0, h1, l1;
    split_pair(v0, v1, h0, l0);
    split_pair(v2, v3, h1, l1);
    size_t ofs = (size_t)row * E_ + c;
    *(uint32_t*)(g_gh + ofs)     = h0;
    *(uint32_t*)(g_gh + ofs + 2) = h1;
    *(uint32_t*)(g_gl + ofs)     = l0;
    *(uint32_t*)(g_gl + ofs + 2) = l1;
}

// ============================================================
extern "C" void kernel_launch(void* const* d_in, const int* in_sizes, int n_in,
                              void* d_out, int out_size)
{
    const float* x    = (const float*)d_in[0];
    const float* Wq   = (const float*)d_in[1];
    const float* bq   = (const float*)d_in[2];
    const float* Wk   = (const float*)d_in[3];
    const float* bk   = (const float*)d_in[4];
    const float* Wv   = (const float*)d_in[5];
    const float* bv   = (const float*)d_in[6];
    const float* Wu   = (const float*)d_in[7];
    const float* bu   = (const float*)d_in[8];
    const float* Wo   = (const float*)d_in[9];
    const float* bo   = (const float*)d_in[10];
    const float* lng  = (const float*)d_in[11];
    const float* lnb  = (const float*)d_in[12];
    float* out = (float*)d_out;

    cudaFuncSetAttribute(mma_gemm, cudaFuncAttributeMaxDynamicSharedMemorySize, 2 * GSTG);
    cudaFuncSetAttribute(mma_attn, cudaFuncAttributeMaxDynamicSharedMemorySize, AT_SMEM);

    fp16 *xh_p, *xl_p, *w_p, *gh_p, *gl_p;
    cudaGetSymbolAddress((void**)&xh_p, g_xh);
    cudaGetSymbolAddress((void**)&xl_p, g_xl);
    cudaGetSymbolAddress((void**)&w_p,  g_w);
    cudaGetSymbolAddress((void**)&gh_p, g_gh);
    cudaGetSymbolAddress((void**)&gl_p, g_gl);

    // 0) convert: x -> split fp16; 5 weights -> fp16 (single launch)
    {
        int n4 = (MTOT * E_) / 4;
        cvt_split<<<n4 / 256, 256>>>((const float4*)x,
            (uint32_t*)xh_p, (uint32_t*)xl_p, n4);
        cvt_w<<<(5 * W4C + 255) / 256, 256>>>(
            (const float4*)Wq, (const float4*)Wk, (const float4*)Wv,
            (const float4*)Wu, (const float4*)Wo, (uint32_t*)w_p);
    }

    // 1) fused QKVU projections: grid x = 4 sectors x 8 n-tiles, y = 32 m-tiles
    mma_gemm<<<dim3(32, 32), 256, 2 * GSTG>>>(
        xh_p, xl_p, bq, bk, bv, bu, nullptr, 0);

    // 2) relu-attention on tensor cores
    mma_attn<<<dim3(16, 32), 256, AT_SMEM>>>();

    // 3) layernorm + gate (writes split fp16)
    ln_gate<<<MTOT, 256>>>(lng, lnb);

    // 4) output projection
    mma_gemm<<<dim3(8, 32), 256, 2 * GSTG>>>(
        gh_p, gl_p, bo, nullptr, nullptr, nullptr, out, 1);
}

// round 16
// speedup vs baseline: 1.5718x; 1.0015x over previous
#include <cuda_runtime.h>
#include <cuda_fp16.h>
#include <cstdint>
#include <math.h>

#define B_    2
#define N_    2048
#define E_    1024
#define H_    16
#define HD_   64
#define MTOT  (B_*N_)          // 4096

typedef __half fp16;

// ---- scratch (device globals; no allocation allowed) ----
__device__ fp16  g_xh[MTOT*E_], g_xl[MTOT*E_];       // split x
__device__ fp16  g_w[5*E_*E_];                        // fp16 Wq,Wk,Wv,Wu,Wo
__device__ fp16  g_qh[B_*H_*N_*HD_], g_ql[B_*H_*N_*HD_]; // q split [bh][n][d]
__device__ fp16  g_k[B_*H_*N_*HD_];                   // k single fp16
__device__ fp16  g_v[B_*H_*N_*HD_];                   // v single fp16 (silu)
__device__ float g_u[MTOT*E_];                        // silu(u), fp32
__device__ float g_attn[MTOT*E_];                     // attention out, fp32
__device__ fp16  g_gh[MTOT*E_], g_gl[MTOT*E_];       // split ln-gated

__device__ __forceinline__ float silu_f(float x) {
    return x / (1.0f + expf(-x));
}

// ============================================================
// helpers
// ============================================================
__device__ __forceinline__ uint32_t smem_u32(const void* p) {
    uint32_t a;
    asm("{ .reg .u64 t; cvta.to.shared.u64 t, %1; cvt.u32.u64 %0, t; }"
        : "=r"(a) : "l"(p));
    return a;
}

__device__ __forceinline__ void cp16(uint32_t smem_dst, const void* gptr) {
    asm volatile("cp.async.cg.shared.global [%0], [%1], 16;"
        :: "r"(smem_dst), "l"(gptr) : "memory");
}
#define CP_COMMIT()  asm volatile("cp.async.commit_group;" ::: "memory")
#define CP_WAIT(n)   asm volatile("cp.async.wait_group %0;" :: "n"(n) : "memory")

__device__ __forceinline__ void ldsm_x4(uint32_t& r0, uint32_t& r1,
                                        uint32_t& r2, uint32_t& r3, uint32_t a) {
    asm volatile("ldmatrix.sync.aligned.m8n8.x4.shared.b16 {%0,%1,%2,%3}, [%4];"
        : "=r"(r0), "=r"(r1), "=r"(r2), "=r"(r3) : "r"(a));
}
__device__ __forceinline__ void ldsm_x4t(uint32_t& r0, uint32_t& r1,
                                         uint32_t& r2, uint32_t& r3, uint32_t a) {
    asm volatile("ldmatrix.sync.aligned.m8n8.x4.trans.shared.b16 {%0,%1,%2,%3}, [%4];"
        : "=r"(r0), "=r"(r1), "=r"(r2), "=r"(r3) : "r"(a));
}

__device__ __forceinline__ void mma_f16(float* c, const uint32_t* a,
                                        uint32_t b0, uint32_t b1) {
    asm volatile(
        "mma.sync.aligned.m16n8k16.row.col.f32.f16.f16.f32 "
        "{%0,%1,%2,%3}, {%4,%5,%6,%7}, {%8,%9}, {%0,%1,%2,%3};"
        : "+f"(c[0]), "+f"(c[1]), "+f"(c[2]), "+f"(c[3])
        : "r"(a[0]), "r"(a[1]), "r"(a[2]), "r"(a[3]), "r"(b0), "r"(b1));
}

// split a pair of floats into hi/lo fp16x2 (packed, elem0 in low half)
__device__ __forceinline__ void split_pair(float v0, float v1,
                                           uint32_t& hi, uint32_t& lo) {
    __half h0 = __float2half_rn(v0);
    __half h1 = __float2half_rn(v1);
    __half l0 = __float2half_rn(v0 - __half2float(h0));
    __half l1 = __float2half_rn(v1 - __half2float(h1));
    __half2 hp = __halves2half2(h0, h1);
    __half2 lp = __halves2half2(l0, l1);
    hi = *reinterpret_cast<uint32_t*>(&hp);
    lo = *reinterpret_cast<uint32_t*>(&lp);
}
__device__ __forceinline__ uint32_t pack_h2(float v0, float v1) {
    __half2 p = __floats2half2_rn(v0, v1);
    return *reinterpret_cast<uint32_t*>(&p);
}

// ============================================================
// fp32 -> split fp16 conversion (x)
// ============================================================
__global__ __launch_bounds__(256) void cvt_split(
    const float4* __restrict__ src, uint32_t* __restrict__ hi,
    uint32_t* __restrict__ lo, int n4)
{
    int i = blockIdx.x * 256 + threadIdx.x;
    if (i >= n4) return;
    float4 v = src[i];
    uint32_t h0, l0, h1, l1;
    split_pair(v.x, v.y, h0, l0);
    split_pair(v.z, v.w, h1, l1);
    hi[2*i]   = h0;  hi[2*i+1] = h1;
    lo[2*i]   = l0;  lo[2*i+1] = l1;
}

// fp32 -> fp16 for all 5 weights, one launch
#define W4C (E_*E_/4)
__global__ __launch_bounds__(256) void cvt_w(
    const float4* __restrict__ w0, const float4* __restrict__ w1,
    const float4* __restrict__ w2, const float4* __restrict__ w3,
    const float4* __restrict__ w4p, uint32_t* __restrict__ dst)
{
    int i = blockIdx.x * 256 + threadIdx.x;
    if (i >= 5 * W4C) return;
    int w = i / W4C, j = i - w * W4C;
    const float4* src = (w == 0) ? w0 : (w == 1) ? w1 : (w == 2) ? w2
                       : (w == 3) ? w3 : w4p;
    float4 v = src[j];
    dst[2*i]   = pack_h2(v.x, v.y);
    dst[2*i+1] = pack_h2(v.z, v.w);
}

// ============================================================
// 2-term split-fp16 MMA GEMM: C[m,n] = sum_k A[m,k]*W[n,k] + bias[n]
// A split (Ah+Al), W single fp16. 128x128 tile, k-tile 32,
// 8 warps (2m x 4n), warp tile 64x32. R12 schedule (prefetch kt+1
// at loop top), x4-paired B ldmatrix. (unchanged from R15)
// ============================================================
#define GSTG 24576

__global__ __launch_bounds__(256) void mma_gemm(
    const fp16* __restrict__ Ah, const fp16* __restrict__ Al,
    const float* __restrict__ bb0, const float* __restrict__ bb1,
    const float* __restrict__ bb2, const float* __restrict__ bb3,
    float* __restrict__ Cout, int mode)
{
    extern __shared__ char smem[];
    const int tid  = threadIdx.x;
    const int lane = tid & 31;
    const int wid  = tid >> 5;
    const int wm   = wid & 1;      // 0..1 -> m offset *64
    const int wn   = wid >> 1;     // 0..3 -> n offset *32

    const int m0 = blockIdx.y * 128;
    const int sector = (mode == 0) ? (int)(blockIdx.x >> 3) : 4;
    const int n0 = (int)(blockIdx.x & 7) * 128;
    const fp16* Wp = g_w + (size_t)sector * (E_ * E_);
    const float* bias = (mode == 1) ? bb0
        : (sector == 0 ? bb0 : sector == 1 ? bb1 : sector == 2 ? bb2 : bb3);

    uint32_t sbase = smem_u32(smem);

    float acc[4][4][4];
#pragma unroll
    for (int a = 0; a < 4; a++)
#pragma unroll
        for (int b = 0; b < 4; b++)
#pragma unroll
            for (int c = 0; c < 4; c++) acc[a][b][c] = 0.0f;

    // tile loader: 512 16B-chunks per matrix (Ah, Al, B), 2/thread each
#define LOAD_TILE(kt, stage) do {                                              \
    uint32_t sb_ = sbase + (uint32_t)(stage) * GSTG;                           \
    int kofs_ = (kt) * 32;                                                     \
    _Pragma("unroll")                                                          \
    for (int j_ = 0; j_ < 2; j_++) {                                           \
        int idx_ = tid + j_ * 256;                                             \
        int r_ = idx_ >> 2, kc_ = idx_ & 3;                                    \
        uint32_t so_ = (uint32_t)(r_ * 64 + ((kc_ ^ (r_ & 3)) << 4));          \
        size_t ga_ = (size_t)(m0 + r_) * E_ + kofs_ + kc_ * 8;                 \
        size_t gb_ = (size_t)(n0 + r_) * E_ + kofs_ + kc_ * 8;                 \
        cp16(sb_ +     0 + so_, Ah + ga_);                                     \
        cp16(sb_ +  8192 + so_, Al + ga_);                                     \
        cp16(sb_ + 16384 + so_, Wp + gb_);                                     \
    }                                                                          \
} while (0)

    LOAD_TILE(0, 0);
    CP_COMMIT();

    const int mtxA = lane >> 3, lrA = lane & 7;

    for (int kt = 0; kt < 32; kt++) {
        if (kt + 1 < 32) { LOAD_TILE(kt + 1, (kt + 1) & 1); CP_COMMIT(); }
        if (kt + 1 < 32) { CP_WAIT(1); } else { CP_WAIT(0); }
        __syncthreads();

        uint32_t sA_h = sbase + (uint32_t)(kt & 1) * GSTG;
        uint32_t sA_l = sA_h + 8192;
        uint32_t sB   = sA_h + 16384;

#pragma unroll
        for (int ks = 0; ks < 2; ks++) {
            uint32_t ahf[4][4], alf[4][4], bf[4][2];
#pragma unroll
            for (int mt = 0; mt < 4; mt++) {
                int row = wm * 64 + mt * 16 + (mtxA & 1) * 8 + lrA;
                int kch = ks * 2 + (mtxA >> 1);
                uint32_t ao = (uint32_t)(row * 64 + ((kch ^ (row & 3)) << 4));
                ldsm_x4(ahf[mt][0], ahf[mt][1], ahf[mt][2], ahf[mt][3], sA_h + ao);
                ldsm_x4(alf[mt][0], alf[mt][1], alf[mt][2], alf[mt][3], sA_l + ao);
            }
            // B: pair two nt tiles per x4 (lanes 0-15 -> nt, 16-31 -> nt+1)
#pragma unroll
            for (int np = 0; np < 2; np++) {
                int nt_eff = np * 2 + (lane >> 4);
                int row = wn * 32 + nt_eff * 8 + (lane & 7);
                int kch = ks * 2 + ((lane >> 3) & 1);
                uint32_t bo = (uint32_t)(row * 64 + ((kch ^ (row & 3)) << 4));
                ldsm_x4(bf[np*2][0], bf[np*2][1], bf[np*2+1][0], bf[np*2+1][1],
                        sB + bo);
            }
#pragma unroll
            for (int mt = 0; mt < 4; mt++)
#pragma unroll
                for (int nt = 0; nt < 4; nt++) {
                    mma_f16(acc[mt][nt], ahf[mt], bf[nt][0], bf[nt][1]);
                    mma_f16(acc[mt][nt], alf[mt], bf[nt][0], bf[nt][1]);
                }
        }
        __syncthreads();
    }

    // ---- epilogue ----
#pragma unroll
    for (int mt = 0; mt < 4; mt++) {
#pragma unroll
        for (int half = 0; half < 2; half++) {
            int m = m0 + wm * 64 + mt * 16 + (lane >> 2) + half * 8;
#pragma unroll
            for (int nt = 0; nt < 4; nt++) {
                int e = n0 + wn * 32 + nt * 8 + (lane & 3) * 2;
                float v0 = acc[mt][nt][half * 2 + 0] + bias[e];
                float v1 = acc[mt][nt][half * 2 + 1] + bias[e + 1];
                if (mode == 1) {
                    float2 o = make_float2(v0, v1);
                    *(float2*)(Cout + (size_t)m * E_ + e) = o;
                } else if (sector == 3) {
                    float2 o = make_float2(silu_f(v0), silu_f(v1));
                    *(float2*)(g_u + (size_t)m * E_ + e) = o;
                } else {
                    int b  = m >> 11;
                    int nn = m & 2047;
                    int h  = e >> 6, d = e & 63;
                    size_t ofs = (((size_t)(b * H_ + h)) * N_ + nn) * HD_ + d;
                    if (sector == 0) {            // q: split
                        uint32_t hi, lo;
                        split_pair(v0, v1, hi, lo);
                        *(uint32_t*)(g_qh + ofs) = hi;
                        *(uint32_t*)(g_ql + ofs) = lo;
                    } else if (sector == 1) {     // k: single
                        *(uint32_t*)(g_k + ofs) = pack_h2(v0, v1);
                    } else {                      // v: silu, single
                        *(uint32_t*)(g_v + ofs) = pack_h2(silu_f(v0), silu_f(v1));
                    }
                }
            }
        }
    }
#undef LOAD_TILE
}

// ============================================================
// 2-term split-fp16 MMA attention: O = relu(Q K^T / 8) V
// Q split: hi persistent in regs, LO RELOADED from smem per chunk
// (frees 16 persistent regs -> double-buffered K/V fits 2 CTAs/SM).
// Double-buffered K/V: wait(1) on KV(ch), KV(ch+1) in flight,
// prefetch KV(ch+2) at loop bottom. Halved-S inner loop.
// smem: Qh,Ql 16KB + K[2],V[2] 16KB each = 96KB.
// ============================================================
#define AT_Q_H  0
#define AT_Q_L  16384
#define AT_K(s) (32768 + (s) * 16384)
#define AT_V(s) (65536 + (s) * 16384)
#define AT_SMEM 98304

__global__ __launch_bounds__(256) void mma_attn()
{
    extern __shared__ char smem[];
    const int tid  = threadIdx.x;
    const int lane = tid & 31;
    const int wid  = tid >> 5;

    const int qt = blockIdx.x;       // 0..15
    const int bh = blockIdx.y;       // 0..31
    const int q0 = qt * 128;
    const size_t bhofs = (size_t)bh * N_ * HD_;

    uint32_t sbase = smem_u32(smem);

    // kv chunk loader into stage s
#define LOAD_KV(ch, s) do {                                                    \
    _Pragma("unroll")                                                          \
    for (int j_ = 0; j_ < 4; j_++) {                                           \
        int idx_ = tid + j_ * 256;                                             \
        int r_ = idx_ >> 3, kc_ = idx_ & 7;                                    \
        uint32_t so_ = (uint32_t)(r_ * 128 + ((kc_ ^ (r_ & 7)) << 4));         \
        size_t g_ = bhofs + (size_t)((ch) * 128 + r_) * HD_ + kc_ * 8;         \
        cp16(sbase + AT_K(s) + so_, g_k + g_);                                 \
        cp16(sbase + AT_V(s) + so_, g_v + g_);                                 \
    }                                                                          \
} while (0)

    // ---- load Q tile (hi+lo), then prologue KV stages 0 and 1 ----
#pragma unroll
    for (int j = 0; j < 4; j++) {
        int idx = tid + j * 256;           // 0..1023
        int r = idx >> 3, kc = idx & 7;
        uint32_t so = (uint32_t)(r * 128 + ((kc ^ (r & 7)) << 4));
        size_t g = bhofs + (size_t)(q0 + r) * HD_ + kc * 8;
        cp16(sbase + AT_Q_H + so, g_qh + g);
        cp16(sbase + AT_Q_L + so, g_ql + g);
    }
    CP_COMMIT();
    LOAD_KV(0, 0); CP_COMMIT();
    LOAD_KV(1, 1); CP_COMMIT();

    CP_WAIT(2);        // Q complete (KV0/KV1 may still be in flight)
    __syncthreads();

    // ---- Q-hi fragments persist in regs; Q-lo reloaded per chunk ----
    uint32_t qfh[4][4];
    {
        const int mtx = lane >> 3, lr = lane & 7;
#pragma unroll
        for (int ks = 0; ks < 4; ks++) {
            int row = wid * 16 + (mtx & 1) * 8 + lr;
            int kch = ks * 2 + (mtx >> 1);
            uint32_t ao = (uint32_t)(row * 128 + ((kch ^ (row & 7)) << 4));
            ldsm_x4(qfh[ks][0], qfh[ks][1], qfh[ks][2], qfh[ks][3], sbase + AT_Q_H + ao);
        }
    }

    float accO[8][4];
#pragma unroll
    for (int i = 0; i < 8; i++)
#pragma unroll
        for (int j = 0; j < 4; j++) accO[i][j] = 0.0f;

    for (int ch = 0; ch < 16; ch++) {
        if (ch < 15) { CP_WAIT(1); } else { CP_WAIT(0); }
        __syncthreads();

        // reload Q-lo fragments (static smem; identical values every chunk)
        uint32_t qfl[4][4];
        {
            const int mtx = lane >> 3, lr = lane & 7;
#pragma unroll
            for (int ks = 0; ks < 4; ks++) {
                int row = wid * 16 + (mtx & 1) * 8 + lr;
                int kch = ks * 2 + (mtx >> 1);
                uint32_t ao = (uint32_t)(row * 128 + ((kch ^ (row & 7)) << 4));
                ldsm_x4(qfl[ks][0], qfl[ks][1], qfl[ks][2], qfl[ks][3],
                        sbase + AT_Q_L + ao);
            }
        }

        uint32_t sK = sbase + AT_K(ch & 1);
        uint32_t sV = sbase + AT_V(ch & 1);

        // two 64-kv halves; S lives only within a half (32 regs)
#pragma unroll
        for (int half = 0; half < 2; half++) {
            float sacc[8][4];
            // ---- S = Q K^T : nt pairs via ldsm x4 ----
#pragma unroll
            for (int np = 0; np < 4; np++) {
#pragma unroll
                for (int i = 0; i < 4; i++) {
                    sacc[np*2][i]   = 0.0f;
                    sacc[np*2+1][i] = 0.0f;
                }
                uint32_t kf[4][4];
#pragma unroll
                for (int ks = 0; ks < 4; ks++) {
                    int nt_eff = half * 8 + np * 2 + (lane >> 4);
                    int row = nt_eff * 8 + (lane & 7);
                    int kch = ks * 2 + ((lane >> 3) & 1);
                    uint32_t bo = (uint32_t)(row * 128 + ((kch ^ (row & 7)) << 4));
                    ldsm_x4(kf[ks][0], kf[ks][1], kf[ks][2], kf[ks][3], sK + bo);
                }
#pragma unroll
                for (int ks = 0; ks < 4; ks++) {
                    mma_f16(sacc[np*2],   qfh[ks], kf[ks][0], kf[ks][1]);
                    mma_f16(sacc[np*2],   qfl[ks], kf[ks][0], kf[ks][1]);
                    mma_f16(sacc[np*2+1], qfh[ks], kf[ks][2], kf[ks][3]);
                    mma_f16(sacc[np*2+1], qfl[ks], kf[ks][2], kf[ks][3]);
                }
            }
            // scale + relu
#pragma unroll
            for (int nt = 0; nt < 8; nt++)
#pragma unroll
                for (int i = 0; i < 4; i++) {
                    float s = sacc[nt][i] * 0.125f;
                    sacc[nt][i] = s > 0.0f ? s : 0.0f;
                }

            // ---- O += S V over this half's 64 kv rows ----
#pragma unroll
            for (int kbl = 0; kbl < 4; kbl++) {
                int kb = half * 4 + kbl;
                uint32_t ah[4], al[4];
                split_pair(sacc[2*kbl][0],   sacc[2*kbl][1],   ah[0], al[0]);
                split_pair(sacc[2*kbl][2],   sacc[2*kbl][3],   ah[1], al[1]);
                split_pair(sacc[2*kbl+1][0], sacc[2*kbl+1][1], ah[2], al[2]);
                split_pair(sacc[2*kbl+1][2], sacc[2*kbl+1][3], ah[3], al[3]);
#pragma unroll
                for (int dp = 0; dp < 4; dp++) {
                    int kvrow = kb * 16 + (lane & 15);
                    int dte = dp * 2 + (lane >> 4);
                    uint32_t vo = (uint32_t)(kvrow * 128 + ((dte ^ (kvrow & 7)) << 4));
                    uint32_t v0, v1, v2, v3;
                    ldsm_x4t(v0, v1, v2, v3, sV + vo);
                    mma_f16(accO[dp*2],   ah, v0, v1);
                    mma_f16(accO[dp*2],   al, v0, v1);
                    mma_f16(accO[dp*2+1], ah, v2, v3);
                    mma_f16(accO[dp*2+1], al, v2, v3);
                }
            }
        }

        __syncthreads();
        if (ch + 2 < 16) { LOAD_KV(ch + 2, ch & 1); CP_COMMIT(); }
    }

    // ---- write O -> g_attn [b][n][h*64+d] ----
    const int b = bh >> 4;
    const int h = bh & 15;
#pragma unroll
    for (int dt = 0; dt < 8; dt++) {
        int d = dt * 8 + (lane & 3) * 2;
#pragma unroll
        for (int half = 0; half < 2; half++) {
            int q = q0 + wid * 16 + (lane >> 2) + half * 8;
            float2 o = make_float2(accO[dt][half * 2], accO[dt][half * 2 + 1]);
            *(float2*)(g_attn + ((size_t)(b * N_ + q)) * E_ + h * HD_ + d) = o;
        }
    }
#undef LOAD_KV
}

// ============================================================
// LayerNorm + gate -> split fp16 (g_gh/g_gl)
// ============================================================
__global__ __launch_bounds__(256) void ln_gate(
    const float* __restrict__ ln_g, const float* __restrict__ ln_b)
{
    const int row = blockIdx.x;
    const int c   = threadIdx.x * 4;
    const float* xr = g_attn + (size_t)row * E_;

    float4 a = *(const float4*)(xr + c);
    float sum = a.x + a.y + a.z + a.w;
    float sq  = a.x * a.x + a.y * a.y + a.z * a.z + a.w * a.w;

#pragma unroll
    for (int off = 16; off > 0; off >>= 1) {
        sum += __shfl_xor_sync(0xffffffff, sum, off);
        sq  += __shfl_xor_sync(0xffffffff, sq,  off);
    }
    __shared__ float s1[8], s2[8];
    int wid = threadIdx.x >> 5, lid = threadIdx.x & 31;
    if (lid == 0) { s1[wid] = sum; s2[wid] = sq; }
    __syncthreads();
    if (threadIdx.x < 8) {
        sum = s1[threadIdx.x]; sq = s2[threadIdx.x];
#pragma unroll
        for (int off = 4; off > 0; off >>= 1) {
            sum += __shfl_xor_sync(0xff, sum, off);
            sq  += __shfl_xor_sync(0xff, sq,  off);
        }
        if (threadIdx.x == 0) { s1[0] = sum; s2[0] = sq; }
    }
    __syncthreads();
    sum = s1[0]; sq = s2[0];

    float mean = sum * (1.0f / E_);
    float var  = sq * (1.0f / E_) - mean * mean;
    float inv  = rsqrtf(var + 1e-5f);

    float4 g4 = *(const float4*)(ln_g + c);
    float4 b4 = *(const float4*)(ln_b + c);
    float4 u4 = *(const float4*)(g_u + (size_t)row * E_ + c);
    float v0 = ((a.x - mean) * inv * g4.x + b4.x) * u4.x;
    float v1 = ((a.y - mean) * inv * g4.y + b4.y) * u4.y;
    float v2 = ((a.z - mean) * inv * g4.z + b4.z) * u4.z;
    float v3 = ((a.w - mean) * inv * g4.w + b4.w) * u4.w;

    uint32_t h0, l0, h1, l1;
    split_pair(v0, v1, h0, l0);
    split_pair(v2, v3, h1, l1);
    size_t ofs = (size_t)row * E_ + c;
    *(uint32_t*)(g_gh + ofs)     = h0;
    *(uint32_t*)(g_gh + ofs + 2) = h1;
    *(uint32_t*)(g_gl + ofs)     = l0;
    *(uint32_t*)(g_gl + ofs + 2) = l1;
}

// ============================================================
extern "C" void kernel_launch(void* const* d_in, const int* in_sizes, int n_in,
                              void* d_out, int out_size)
{
    const float* x    = (const float*)d_in[0];
    const float* Wq   = (const float*)d_in[1];
    const float* bq   = (const float*)d_in[2];
    const float* Wk   = (const float*)d_in[3];
    const float* bk   = (const float*)d_in[4];
    const float* Wv   = (const float*)d_in[5];
    const float* bv   = (const float*)d_in[6];
    const float* Wu   = (const float*)d_in[7];
    const float* bu   = (const float*)d_in[8];
    const float* Wo   = (const float*)d_in[9];
    const float* bo   = (const float*)d_in[10];
    const float* lng  = (const float*)d_in[11];
    const float* lnb  = (const float*)d_in[12];
    float* out = (float*)d_out;

    cudaFuncSetAttribute(mma_gemm, cudaFuncAttributeMaxDynamicSharedMemorySize, 2 * GSTG);
    cudaFuncSetAttribute(mma_attn, cudaFuncAttributeMaxDynamicSharedMemorySize, AT_SMEM);

    fp16 *xh_p, *xl_p, *w_p, *gh_p, *gl_p;
    cudaGetSymbolAddress((void**)&xh_p, g_xh);
    cudaGetSymbolAddress((void**)&xl_p, g_xl);
    cudaGetSymbolAddress((void**)&w_p,  g_w);
    cudaGetSymbolAddress((void**)&gh_p, g_gh);
    cudaGetSymbolAddress((void**)&gl_p, g_gl);

    // 0) convert: x -> split fp16; 5 weights -> fp16 (single launch)
    {
        int n4 = (MTOT * E_) / 4;
        cvt_split<<<n4 / 256, 256>>>((const float4*)x,
            (uint32_t*)xh_p, (uint32_t*)xl_p, n4);
        cvt_w<<<(5 * W4C + 255) / 256, 256>>>(
            (const float4*)Wq, (const float4*)Wk, (const float4*)Wv,
            (const float4*)Wu, (const float4*)Wo, (uint32_t*)w_p);
    }

    // 1) fused QKVU projections: grid x = 4 sectors x 8 n-tiles, y = 32 m-tiles
    mma_gemm<<<dim3(32, 32), 256, 2 * GSTG>>>(
        xh_p, xl_p, bq, bk, bv, bu, nullptr, 0);

    // 2) relu-attention on tensor cores
    mma_attn<<<dim3(16, 32), 256, AT_SMEM>>>();

    // 3) layernorm + gate (writes split fp16)
    ln_gate<<<MTOT, 256>>>(lng, lnb);

    // 4) output projection
    mma_gemm<<<dim3(8, 32), 256, 2 * GSTG>>>(
        gh_p, gl_p, bo, nullptr, nullptr, nullptr, out, 1);
}